// round 1
// baseline (speedup 1.0000x reference)
#include <cuda_runtime.h>
#include <cstdint>

// ---------------- problem-size constants (fixed by the dataset) ----------------
#define MAX_NODES 100000
#define MAX_EDGES 1000000
#define FEAT      64            // IN_FEATS == N_CLASSES == 64
#define SCAN_BLK  1024
#define MAX_SCAN_BLOCKS ((MAX_NODES + SCAN_BLK - 1) / SCAN_BLK)   // 98

// ---------------- device scratch (no allocations allowed) ----------------
__device__ int   g_deg[MAX_NODES];
__device__ int   g_off[MAX_NODES + 1];
__device__ int   g_cur[MAX_NODES];
__device__ int   g_sorted[MAX_EDGES];
__device__ int   g_blocksums[MAX_SCAN_BLOCKS + 1];
// zy[row][0..63]  = x @ W_self + b   (z, used at dst)
// zy[row][64..127]= x @ W_neigh      (y, gathered via src)
__device__ float g_zy[(size_t)MAX_NODES * 128];

// ---------------- 1) zero degree array ----------------
__global__ void k_zero_deg(int n) {
    int i = blockIdx.x * blockDim.x + threadIdx.x;
    if (i < n) g_deg[i] = 0;
}

// ---------------- 2) degree histogram ----------------
__global__ void k_hist(const int* __restrict__ dst, int n_edges) {
    int e = blockIdx.x * blockDim.x + threadIdx.x;
    if (e < n_edges) atomicAdd(&g_deg[dst[e]], 1);
}

// ---------------- 3a) per-block exclusive scan of degrees ----------------
__global__ void k_scan1(int n) {
    __shared__ int ws[32];
    int i    = blockIdx.x * SCAN_BLK + threadIdx.x;
    int lane = threadIdx.x & 31;
    int wid  = threadIdx.x >> 5;
    int v    = (i < n) ? g_deg[i] : 0;
    int orig = v;
    #pragma unroll
    for (int o = 1; o < 32; o <<= 1) {
        int t = __shfl_up_sync(0xffffffffu, v, o);
        if (lane >= o) v += t;
    }
    if (lane == 31) ws[wid] = v;
    __syncthreads();
    if (wid == 0) {
        int w = ws[lane];
        #pragma unroll
        for (int o = 1; o < 32; o <<= 1) {
            int t = __shfl_up_sync(0xffffffffu, w, o);
            if (lane >= o) w += t;
        }
        ws[lane] = w;
    }
    __syncthreads();
    int base = wid ? ws[wid - 1] : 0;
    if (i < n) g_off[i] = base + v - orig;           // exclusive within block
    if (threadIdx.x == 0) g_blocksums[blockIdx.x] = ws[31];
}

// ---------------- 3b) scan of block sums (tiny, serial) ----------------
__global__ void k_scan2(int nb) {
    if (threadIdx.x == 0 && blockIdx.x == 0) {
        int c = 0;
        for (int b = 0; b < nb; b++) {
            int t = g_blocksums[b];
            g_blocksums[b] = c;
            c += t;
        }
    }
}

// ---------------- 3c) add block offsets; init cursors ----------------
__global__ void k_scan3(int num_dst, int n_edges) {
    int i = blockIdx.x * blockDim.x + threadIdx.x;
    if (i < num_dst) {
        int o = g_off[i] + g_blocksums[i >> 10];
        g_off[i] = o;
        g_cur[i] = o;
    }
    if (i == 0) g_off[num_dst] = n_edges;
}

// ---------------- 4) counting-sort scatter of src indices ----------------
__global__ void k_scatter(const int* __restrict__ src, const int* __restrict__ dst,
                          int n_edges) {
    int e = blockIdx.x * blockDim.x + threadIdx.x;
    if (e < n_edges) {
        int d = dst[e];
        int p = atomicAdd(&g_cur[d], 1);
        g_sorted[p] = src[e];
    }
}

// ---------------- 5) zy = [ x@W_self + b | x@W_neigh ] ----------------
// block: 256 threads computes a 64-row x 128-col tile; K = 64 (full).
__global__ __launch_bounds__(256) void k_gemm_zy(
    const float* __restrict__ x,
    const float* __restrict__ Ws,
    const float* __restrict__ Wn,
    const float* __restrict__ b,
    int n)
{
    __shared__ float sX[64][64];     // 16 KB
    __shared__ float sW[64][128];    // 32 KB
    __shared__ float sB[64];

    int tid = threadIdx.x;
    int r0  = blockIdx.x * 64;

    // load W_self | W_neigh into sW (2048 float4)
    for (int i = tid; i < 2048; i += 256) {
        int k  = i >> 5;          // row (0..63)
        int c4 = i & 31;          // float4 index within 128-float row
        float4 v = (c4 < 16) ? ((const float4*)Ws)[k * 16 + c4]
                             : ((const float4*)Wn)[k * 16 + (c4 - 16)];
        ((float4*)&sW[k][0])[c4] = v;
    }
    if (tid < 64) sB[tid] = b[tid];

    // load 64x64 tile of x (1024 float4), zero-pad OOB rows
    for (int i = tid; i < 1024; i += 256) {
        int r  = i >> 4;
        int c4 = i & 15;
        int gr = r0 + r;
        float4 v = make_float4(0.f, 0.f, 0.f, 0.f);
        if (gr < n) v = ((const float4*)x)[(size_t)gr * 16 + c4];
        ((float4*)&sX[r][0])[c4] = v;
    }
    __syncthreads();

    int cg = (tid & 31) * 4;      // column group: 0..124 step 4
    int rg = (tid >> 5) * 8;      // row group: 0..56 step 8

    float acc[8][4];
    #pragma unroll
    for (int i = 0; i < 8; i++)
        #pragma unroll
        for (int j = 0; j < 4; j++) acc[i][j] = 0.f;

    #pragma unroll 8
    for (int k = 0; k < 64; k++) {
        float4 bv = *(const float4*)&sW[k][cg];
        #pragma unroll
        for (int i = 0; i < 8; i++) {
            float a = sX[rg + i][k];
            acc[i][0] += a * bv.x;
            acc[i][1] += a * bv.y;
            acc[i][2] += a * bv.z;
            acc[i][3] += a * bv.w;
        }
    }

    // bias only applies to the z half (cols 0..63)
    float4 bias = make_float4(0.f, 0.f, 0.f, 0.f);
    if (cg < 64) bias = *(const float4*)&sB[cg];

    #pragma unroll
    for (int i = 0; i < 8; i++) {
        int gr = r0 + rg + i;
        if (gr < n) {
            float4 o;
            o.x = acc[i][0] + bias.x;
            o.y = acc[i][1] + bias.y;
            o.z = acc[i][2] + bias.z;
            o.w = acc[i][3] + bias.w;
            *(float4*)&g_zy[(size_t)gr * 128 + cg] = o;
        }
    }
}

// ---------------- 6) per-dst aggregation + epilogue ----------------
// one warp per destination node; gathers y-half rows of zy via CSR.
__global__ __launch_bounds__(256) void k_aggregate(float* __restrict__ out, int num_dst) {
    int warp = (blockIdx.x * blockDim.x + threadIdx.x) >> 5;
    int lane = threadIdx.x & 31;
    if (warp >= num_dst) return;

    int beg = g_off[warp];
    int end = g_off[warp + 1];

    float a0 = 0.f, a1 = 0.f;
    for (int j = beg; j < end; j++) {
        int s = g_sorted[j];
        const float* p = g_zy + (size_t)s * 128 + 64;   // y-half
        a0 += __ldg(p + lane);
        a1 += __ldg(p + 32 + lane);
    }
    int deg = end - beg;
    float inv = 1.0f / (float)(deg > 0 ? deg : 1);

    const float* pz = g_zy + (size_t)warp * 128;        // z-half (has bias)
    float o0 = fmaxf(__ldg(pz + lane)      + a0 * inv, 0.f);
    float o1 = fmaxf(__ldg(pz + 32 + lane) + a1 * inv, 0.f);

    out[(size_t)warp * 64 + lane]      = o0;
    out[(size_t)warp * 64 + 32 + lane] = o1;
}

// ---------------- launch ----------------
extern "C" void kernel_launch(void* const* d_in, const int* in_sizes, int n_in,
                              void* d_out, int out_size) {
    const float* x  = (const float*)d_in[0];
    const float* Ws = (const float*)d_in[1];
    const float* Wn = (const float*)d_in[2];
    const float* b  = (const float*)d_in[3];
    const int*   src = (const int*)d_in[4];
    const int*   dst = (const int*)d_in[5];

    int n_src   = in_sizes[0] / FEAT;
    int n_edges = in_sizes[4];
    int num_dst = out_size / FEAT;
    float* out  = (float*)d_out;

    int tb = 256;
    int gb_nodes = (num_dst + tb - 1) / tb;
    int gb_edges = (n_edges + tb - 1) / tb;
    int nb_scan  = (num_dst + SCAN_BLK - 1) / SCAN_BLK;

    k_zero_deg<<<gb_nodes, tb>>>(num_dst);
    k_hist<<<gb_edges, tb>>>(dst, n_edges);
    k_scan1<<<nb_scan, SCAN_BLK>>>(num_dst);
    k_scan2<<<1, 32>>>(nb_scan);
    k_scan3<<<gb_nodes, tb>>>(num_dst, n_edges);
    k_scatter<<<gb_edges, tb>>>(src, dst, n_edges);

    int gemm_blocks = (n_src + 63) / 64;
    k_gemm_zy<<<gemm_blocks, 256>>>(x, Ws, Wn, b, n_src);

    int agg_blocks = (num_dst * 32 + tb - 1) / tb;   // one warp per dst
    k_aggregate<<<agg_blocks, tb>>>(out, num_dst);
}

// round 2
// speedup vs baseline: 1.5513x; 1.5513x over previous
#include <cuda_runtime.h>
#include <cstdint>

typedef unsigned long long u64;

// ---------------- problem-size constants ----------------
#define MAX_NODES 100000
#define MAX_EDGES 1000000
#define FEAT      64
#define SCAN_BLK  1024
#define MAX_SCAN_BLOCKS ((MAX_NODES + SCAN_BLK - 1) / SCAN_BLK)   // 98

// ---------------- device scratch ----------------
__device__ int   g_deg[MAX_NODES];
__device__ int   g_off[MAX_NODES + 1];
__device__ int   g_cur[MAX_NODES];
__device__ int   g_sorted[MAX_EDGES];
__device__ int   g_blocksums[MAX_SCAN_BLOCKS + 1];
// zy[row][0..63]  = x @ W_self + b   (z, used at dst)
// zy[row][64..127]= x @ W_neigh      (y, gathered via src)
__device__ float g_zy[(size_t)MAX_NODES * 128];

// ---------------- packed f32x2 helpers (Blackwell FFMA2) ----------------
__device__ __forceinline__ u64 f32x2_dup(float a) {
    u64 r;
    asm("mov.b64 %0, {%1, %1};" : "=l"(r) : "f"(a));
    return r;
}
__device__ __forceinline__ u64 f32x2_fma(u64 a, u64 b, u64 c) {
    u64 d;
    asm("fma.rn.f32x2 %0, %1, %2, %3;" : "=l"(d) : "l"(a), "l"(b), "l"(c));
    return d;
}
__device__ __forceinline__ u64 f32x2_add(u64 a, u64 b) {
    u64 d;
    asm("add.rn.f32x2 %0, %1, %2;" : "=l"(d) : "l"(a), "l"(b));
    return d;
}
__device__ __forceinline__ void f32x2_unpack(u64 v, float& lo, float& hi) {
    asm("mov.b64 {%0, %1}, %2;" : "=f"(lo), "=f"(hi) : "l"(v));
}

// ---------------- 1) zero degree array ----------------
__global__ void k_zero_deg(int n) {
    int i = blockIdx.x * blockDim.x + threadIdx.x;
    if (i < n) g_deg[i] = 0;
}

// ---------------- 2) degree histogram ----------------
__global__ void k_hist(const int* __restrict__ dst, int n_edges) {
    int e = blockIdx.x * blockDim.x + threadIdx.x;
    if (e < n_edges) atomicAdd(&g_deg[dst[e]], 1);
}

// ---------------- 3a) per-block exclusive scan of degrees ----------------
__global__ void k_scan1(int n) {
    __shared__ int ws[32];
    int i    = blockIdx.x * SCAN_BLK + threadIdx.x;
    int lane = threadIdx.x & 31;
    int wid  = threadIdx.x >> 5;
    int v    = (i < n) ? g_deg[i] : 0;
    int orig = v;
    #pragma unroll
    for (int o = 1; o < 32; o <<= 1) {
        int t = __shfl_up_sync(0xffffffffu, v, o);
        if (lane >= o) v += t;
    }
    if (lane == 31) ws[wid] = v;
    __syncthreads();
    if (wid == 0) {
        int w = ws[lane];
        #pragma unroll
        for (int o = 1; o < 32; o <<= 1) {
            int t = __shfl_up_sync(0xffffffffu, w, o);
            if (lane >= o) w += t;
        }
        ws[lane] = w;
    }
    __syncthreads();
    int base = wid ? ws[wid - 1] : 0;
    if (i < n) g_off[i] = base + v - orig;
    if (threadIdx.x == 0) g_blocksums[blockIdx.x] = ws[31];
}

// ---------------- 3b) scan of block sums (parallel, 1 block) ----------------
__global__ void k_scan2(int nb) {
    __shared__ int ws[4];
    int i    = threadIdx.x;            // 128 threads, nb <= 128
    int lane = i & 31;
    int wid  = i >> 5;
    int v    = (i < nb) ? g_blocksums[i] : 0;
    int orig = v;
    #pragma unroll
    for (int o = 1; o < 32; o <<= 1) {
        int t = __shfl_up_sync(0xffffffffu, v, o);
        if (lane >= o) v += t;
    }
    if (lane == 31) ws[wid] = v;
    __syncthreads();
    int base = 0;
    for (int w = 0; w < wid; w++) base += ws[w];
    if (i < nb) g_blocksums[i] = base + v - orig;    // exclusive
}

// ---------------- 3c) add block offsets; init cursors ----------------
__global__ void k_scan3(int num_dst, int n_edges) {
    int i = blockIdx.x * blockDim.x + threadIdx.x;
    if (i < num_dst) {
        int o = g_off[i] + g_blocksums[i >> 10];
        g_off[i] = o;
        g_cur[i] = o;
    }
    if (i == 0) g_off[num_dst] = n_edges;
}

// ---------------- 4) counting-sort scatter of src indices ----------------
__global__ void k_scatter(const int* __restrict__ src, const int* __restrict__ dst,
                          int n_edges) {
    int e = blockIdx.x * blockDim.x + threadIdx.x;
    if (e < n_edges) {
        int d = dst[e];
        int p = atomicAdd(&g_cur[d], 1);
        g_sorted[p] = src[e];
    }
}

// ---------------- 5) zy = [ x@W_self + b | x@W_neigh ], FFMA2 tile ----------------
// block: 256 threads, 64-row x 128-col tile, K = 64.
// Accumulators packed over ROW pairs via fma.rn.f32x2.
#define XT_PITCH 66
__global__ __launch_bounds__(256) void k_gemm_zy(
    const float* __restrict__ x,
    const float* __restrict__ Ws,
    const float* __restrict__ Wn,
    const float* __restrict__ b,
    int n)
{
    __shared__ float sXT[64][XT_PITCH];   // transposed: sXT[k][row]
    __shared__ float sW[64][128];
    __shared__ float sB[64];

    int tid = threadIdx.x;
    int r0  = blockIdx.x * 64;

    // load W_self | W_neigh into sW
    for (int i = tid; i < 2048; i += 256) {
        int k  = i >> 5;
        int c4 = i & 31;
        float4 v = (c4 < 16) ? ((const float4*)Ws)[k * 16 + c4]
                             : ((const float4*)Wn)[k * 16 + (c4 - 16)];
        ((float4*)&sW[k][0])[c4] = v;
    }
    if (tid < 64) sB[tid] = b[tid];

    // load 64x64 tile of x, transposed into sXT[k][r]
    for (int i = tid; i < 1024; i += 256) {
        int r  = i >> 4;
        int c4 = i & 15;
        int gr = r0 + r;
        float4 v = make_float4(0.f, 0.f, 0.f, 0.f);
        if (gr < n) v = ((const float4*)x)[(size_t)gr * 16 + c4];
        int k = c4 * 4;
        sXT[k + 0][r] = v.x;
        sXT[k + 1][r] = v.y;
        sXT[k + 2][r] = v.z;
        sXT[k + 3][r] = v.w;
    }
    __syncthreads();

    int cg = (tid & 31) * 4;      // 4 output columns
    int rg = (tid >> 5) * 8;      // 8 output rows = 4 row-pairs

    u64 acc[4][4];                // [rowpair][col], each = 2 rows packed
    #pragma unroll
    for (int t = 0; t < 4; t++)
        #pragma unroll
        for (int c = 0; c < 4; c++) acc[t][c] = 0ull;

    #pragma unroll 4
    for (int k = 0; k < 64; k++) {
        u64 a2[4];
        #pragma unroll
        for (int t = 0; t < 4; t++)
            a2[t] = *(const u64*)&sXT[k][rg + 2 * t];   // (row, row+1) packed

        float4 wv = *(const float4*)&sW[k][cg];
        u64 w0 = f32x2_dup(wv.x);
        u64 w1 = f32x2_dup(wv.y);
        u64 w2 = f32x2_dup(wv.z);
        u64 w3 = f32x2_dup(wv.w);

        #pragma unroll
        for (int t = 0; t < 4; t++) {
            acc[t][0] = f32x2_fma(a2[t], w0, acc[t][0]);
            acc[t][1] = f32x2_fma(a2[t], w1, acc[t][1]);
            acc[t][2] = f32x2_fma(a2[t], w2, acc[t][2]);
            acc[t][3] = f32x2_fma(a2[t], w3, acc[t][3]);
        }
    }

    float4 bias = make_float4(0.f, 0.f, 0.f, 0.f);
    if (cg < 64) bias = *(const float4*)&sB[cg];

    #pragma unroll
    for (int t = 0; t < 4; t++) {
        float lo[4], hi[4];
        #pragma unroll
        for (int c = 0; c < 4; c++) f32x2_unpack(acc[t][c], lo[c], hi[c]);
        int gr0 = r0 + rg + 2 * t;
        if (gr0 < n) {
            float4 o0 = make_float4(lo[0] + bias.x, lo[1] + bias.y,
                                    lo[2] + bias.z, lo[3] + bias.w);
            *(float4*)&g_zy[(size_t)gr0 * 128 + cg] = o0;
        }
        if (gr0 + 1 < n) {
            float4 o1 = make_float4(hi[0] + bias.x, hi[1] + bias.y,
                                    hi[2] + bias.z, hi[3] + bias.w);
            *(float4*)&g_zy[(size_t)(gr0 + 1) * 128 + cg] = o1;
        }
    }
}

// ---------------- 6) per-dst aggregation + epilogue ----------------
// one warp per dst; lane handles feature pair (2*lane, 2*lane+1).
__global__ __launch_bounds__(256) void k_aggregate(float* __restrict__ out, int num_dst) {
    int warp = (blockIdx.x * blockDim.x + threadIdx.x) >> 5;
    int lane = threadIdx.x & 31;
    if (warp >= num_dst) return;

    int beg = g_off[warp];
    int end = g_off[warp + 1];

    u64 a0 = 0ull, a1 = 0ull;     // dual accumulators for ILP
    int j = beg;
    for (; j + 1 < end; j += 2) {
        int s0 = g_sorted[j];
        int s1 = g_sorted[j + 1];
        u64 v0 = *(const u64*)(g_zy + (size_t)s0 * 128 + 64 + 2 * lane);
        u64 v1 = *(const u64*)(g_zy + (size_t)s1 * 128 + 64 + 2 * lane);
        a0 = f32x2_add(a0, v0);
        a1 = f32x2_add(a1, v1);
    }
    if (j < end) {
        int s0 = g_sorted[j];
        u64 v0 = *(const u64*)(g_zy + (size_t)s0 * 128 + 64 + 2 * lane);
        a0 = f32x2_add(a0, v0);
    }
    a0 = f32x2_add(a0, a1);

    float sx, sy;
    f32x2_unpack(a0, sx, sy);

    int deg = end - beg;
    float inv = 1.0f / (float)(deg > 0 ? deg : 1);

    float2 z = *(const float2*)(g_zy + (size_t)warp * 128 + 2 * lane);
    float2 o;
    o.x = fmaxf(z.x + sx * inv, 0.f);
    o.y = fmaxf(z.y + sy * inv, 0.f);
    *(float2*)(out + (size_t)warp * 64 + 2 * lane) = o;
}

// ---------------- launch ----------------
extern "C" void kernel_launch(void* const* d_in, const int* in_sizes, int n_in,
                              void* d_out, int out_size) {
    const float* x  = (const float*)d_in[0];
    const float* Ws = (const float*)d_in[1];
    const float* Wn = (const float*)d_in[2];
    const float* b  = (const float*)d_in[3];
    const int*   src = (const int*)d_in[4];
    const int*   dst = (const int*)d_in[5];

    int n_src   = in_sizes[0] / FEAT;
    int n_edges = in_sizes[4];
    int num_dst = out_size / FEAT;
    float* out  = (float*)d_out;

    int tb = 256;
    int gb_nodes = (num_dst + tb - 1) / tb;
    int gb_edges = (n_edges + tb - 1) / tb;
    int nb_scan  = (num_dst + SCAN_BLK - 1) / SCAN_BLK;

    k_zero_deg<<<gb_nodes, tb>>>(num_dst);
    k_hist<<<gb_edges, tb>>>(dst, n_edges);
    k_scan1<<<nb_scan, SCAN_BLK>>>(num_dst);
    k_scan2<<<1, 128>>>(nb_scan);
    k_scan3<<<gb_nodes, tb>>>(num_dst, n_edges);
    k_scatter<<<gb_edges, tb>>>(src, dst, n_edges);

    int gemm_blocks = (n_src + 63) / 64;
    k_gemm_zy<<<gemm_blocks, 256>>>(x, Ws, Wn, b, n_src);

    int agg_blocks = (num_dst * 32 + tb - 1) / tb;
    k_aggregate<<<agg_blocks, tb>>>(out, num_dst);
}

// round 3
// speedup vs baseline: 1.5569x; 1.0036x over previous
#include <cuda_runtime.h>
#include <cstdint>

typedef unsigned long long u64;

// ---------------- problem-size constants ----------------
#define MAX_NODES 100000
#define MAX_EDGES 1000000
#define FEAT      64
#define SCAN_BLK  1024
#define MAX_SCAN_BLOCKS ((MAX_NODES + SCAN_BLK - 1) / SCAN_BLK)   // 98

// ---------------- device scratch ----------------
__device__ int   g_deg[MAX_NODES];
__device__ int   g_off[MAX_NODES + 1];
__device__ int   g_cur[MAX_NODES];
__device__ int   g_sorted[MAX_EDGES];
__device__ int   g_blocksums[MAX_SCAN_BLOCKS + 1];
// zy[row][0..63]  = x @ W_self + b   (z, used at dst)
// zy[row][64..127]= x @ W_neigh      (y, gathered via src)
__device__ float g_zy[(size_t)MAX_NODES * 128];

// ---------------- packed f32x2 helpers (Blackwell FFMA2) ----------------
__device__ __forceinline__ u64 f32x2_dup(float a) {
    u64 r;
    asm("mov.b64 %0, {%1, %1};" : "=l"(r) : "f"(a));
    return r;
}
__device__ __forceinline__ u64 f32x2_fma(u64 a, u64 b, u64 c) {
    u64 d;
    asm("fma.rn.f32x2 %0, %1, %2, %3;" : "=l"(d) : "l"(a), "l"(b), "l"(c));
    return d;
}
__device__ __forceinline__ u64 f32x2_add(u64 a, u64 b) {
    u64 d;
    asm("add.rn.f32x2 %0, %1, %2;" : "=l"(d) : "l"(a), "l"(b));
    return d;
}
__device__ __forceinline__ void f32x2_unpack(u64 v, float& lo, float& hi) {
    asm("mov.b64 {%0, %1}, %2;" : "=f"(lo), "=f"(hi) : "l"(v));
}

// ---------------- 1) zero degree array ----------------
__global__ void k_zero_deg(int n) {
    int i = blockIdx.x * blockDim.x + threadIdx.x;
    if (i < n) g_deg[i] = 0;
}

// ---------------- 2) degree histogram ----------------
__global__ void k_hist(const int* __restrict__ dst, int n_edges) {
    int e = blockIdx.x * blockDim.x + threadIdx.x;
    if (e < n_edges) atomicAdd(&g_deg[dst[e]], 1);
}

// ---------------- 3a) per-block exclusive scan of degrees ----------------
__global__ void k_scan1(int n) {
    __shared__ int ws[32];
    int i    = blockIdx.x * SCAN_BLK + threadIdx.x;
    int lane = threadIdx.x & 31;
    int wid  = threadIdx.x >> 5;
    int v    = (i < n) ? g_deg[i] : 0;
    int orig = v;
    #pragma unroll
    for (int o = 1; o < 32; o <<= 1) {
        int t = __shfl_up_sync(0xffffffffu, v, o);
        if (lane >= o) v += t;
    }
    if (lane == 31) ws[wid] = v;
    __syncthreads();
    if (wid == 0) {
        int w = ws[lane];
        #pragma unroll
        for (int o = 1; o < 32; o <<= 1) {
            int t = __shfl_up_sync(0xffffffffu, w, o);
            if (lane >= o) w += t;
        }
        ws[lane] = w;
    }
    __syncthreads();
    int base = wid ? ws[wid - 1] : 0;
    if (i < n) g_off[i] = base + v - orig;
    if (threadIdx.x == 0) g_blocksums[blockIdx.x] = ws[31];
}

// ---------------- 3b) scan of block sums (parallel, 1 block) ----------------
__global__ void k_scan2(int nb) {
    __shared__ int ws[4];
    int i    = threadIdx.x;            // 128 threads, nb <= 128
    int lane = i & 31;
    int wid  = i >> 5;
    int v    = (i < nb) ? g_blocksums[i] : 0;
    int orig = v;
    #pragma unroll
    for (int o = 1; o < 32; o <<= 1) {
        int t = __shfl_up_sync(0xffffffffu, v, o);
        if (lane >= o) v += t;
    }
    if (lane == 31) ws[wid] = v;
    __syncthreads();
    int base = 0;
    for (int w = 0; w < wid; w++) base += ws[w];
    if (i < nb) g_blocksums[i] = base + v - orig;    // exclusive
}

// ---------------- 3c) add block offsets; init cursors ----------------
__global__ void k_scan3(int num_dst, int n_edges) {
    int i = blockIdx.x * blockDim.x + threadIdx.x;
    if (i < num_dst) {
        int o = g_off[i] + g_blocksums[i >> 10];
        g_off[i] = o;
        g_cur[i] = o;
    }
    if (i == 0) g_off[num_dst] = n_edges;
}

// ---------------- 4) counting-sort scatter of src indices ----------------
__global__ void k_scatter(const int* __restrict__ src, const int* __restrict__ dst,
                          int n_edges) {
    int e = blockIdx.x * blockDim.x + threadIdx.x;
    if (e < n_edges) {
        int d = dst[e];
        int p = atomicAdd(&g_cur[d], 1);
        g_sorted[p] = src[e];
    }
}

// ---------------- 5) zy = [ x@W_self + b | x@W_neigh ], FFMA2 tile ----------------
#define XT_PITCH 66
__global__ __launch_bounds__(256) void k_gemm_zy(
    const float* __restrict__ x,
    const float* __restrict__ Ws,
    const float* __restrict__ Wn,
    const float* __restrict__ b,
    int n)
{
    __shared__ float sXT[64][XT_PITCH];   // transposed: sXT[k][row]
    __shared__ float sW[64][128];
    __shared__ float sB[64];

    int tid = threadIdx.x;
    int r0  = blockIdx.x * 64;

    for (int i = tid; i < 2048; i += 256) {
        int k  = i >> 5;
        int c4 = i & 31;
        float4 v = (c4 < 16) ? ((const float4*)Ws)[k * 16 + c4]
                             : ((const float4*)Wn)[k * 16 + (c4 - 16)];
        ((float4*)&sW[k][0])[c4] = v;
    }
    if (tid < 64) sB[tid] = b[tid];

    for (int i = tid; i < 1024; i += 256) {
        int r  = i >> 4;
        int c4 = i & 15;
        int gr = r0 + r;
        float4 v = make_float4(0.f, 0.f, 0.f, 0.f);
        if (gr < n) v = ((const float4*)x)[(size_t)gr * 16 + c4];
        int k = c4 * 4;
        sXT[k + 0][r] = v.x;
        sXT[k + 1][r] = v.y;
        sXT[k + 2][r] = v.z;
        sXT[k + 3][r] = v.w;
    }
    __syncthreads();

    int cg = (tid & 31) * 4;      // 4 output columns
    int rg = (tid >> 5) * 8;      // 8 output rows = 4 row-pairs

    u64 acc[4][4];
    #pragma unroll
    for (int t = 0; t < 4; t++)
        #pragma unroll
        for (int c = 0; c < 4; c++) acc[t][c] = 0ull;

    #pragma unroll 4
    for (int k = 0; k < 64; k++) {
        u64 a2[4];
        #pragma unroll
        for (int t = 0; t < 4; t++)
            a2[t] = *(const u64*)&sXT[k][rg + 2 * t];

        float4 wv = *(const float4*)&sW[k][cg];
        u64 w0 = f32x2_dup(wv.x);
        u64 w1 = f32x2_dup(wv.y);
        u64 w2 = f32x2_dup(wv.z);
        u64 w3 = f32x2_dup(wv.w);

        #pragma unroll
        for (int t = 0; t < 4; t++) {
            acc[t][0] = f32x2_fma(a2[t], w0, acc[t][0]);
            acc[t][1] = f32x2_fma(a2[t], w1, acc[t][1]);
            acc[t][2] = f32x2_fma(a2[t], w2, acc[t][2]);
            acc[t][3] = f32x2_fma(a2[t], w3, acc[t][3]);
        }
    }

    float4 bias = make_float4(0.f, 0.f, 0.f, 0.f);
    if (cg < 64) bias = *(const float4*)&sB[cg];

    #pragma unroll
    for (int t = 0; t < 4; t++) {
        float lo[4], hi[4];
        #pragma unroll
        for (int c = 0; c < 4; c++) f32x2_unpack(acc[t][c], lo[c], hi[c]);
        int gr0 = r0 + rg + 2 * t;
        if (gr0 < n) {
            float4 o0 = make_float4(lo[0] + bias.x, lo[1] + bias.y,
                                    lo[2] + bias.z, lo[3] + bias.w);
            *(float4*)&g_zy[(size_t)gr0 * 128 + cg] = o0;
        }
        if (gr0 + 1 < n) {
            float4 o1 = make_float4(hi[0] + bias.x, hi[1] + bias.y,
                                    hi[2] + bias.z, hi[3] + bias.w);
            *(float4*)&g_zy[(size_t)(gr0 + 1) * 128 + cg] = o1;
        }
    }
}

// ---------------- 6) per-dst aggregation + epilogue ----------------
// one warp per dst; lane handles feature pair (2*lane, 2*lane+1).
// 4-deep unroll: 4 independent packed accumulators for memory-level parallelism.
__global__ __launch_bounds__(256) void k_aggregate(float* __restrict__ out, int num_dst) {
    int warp = (blockIdx.x * blockDim.x + threadIdx.x) >> 5;
    int lane = threadIdx.x & 31;
    if (warp >= num_dst) return;

    int beg = g_off[warp];
    int end = g_off[warp + 1];

    u64 a0 = 0ull, a1 = 0ull, a2 = 0ull, a3 = 0ull;
    int j = beg;
    for (; j + 3 < end; j += 4) {
        int s0 = g_sorted[j];
        int s1 = g_sorted[j + 1];
        int s2 = g_sorted[j + 2];
        int s3 = g_sorted[j + 3];
        u64 v0 = *(const u64*)(g_zy + (size_t)s0 * 128 + 64 + 2 * lane);
        u64 v1 = *(const u64*)(g_zy + (size_t)s1 * 128 + 64 + 2 * lane);
        u64 v2 = *(const u64*)(g_zy + (size_t)s2 * 128 + 64 + 2 * lane);
        u64 v3 = *(const u64*)(g_zy + (size_t)s3 * 128 + 64 + 2 * lane);
        a0 = f32x2_add(a0, v0);
        a1 = f32x2_add(a1, v1);
        a2 = f32x2_add(a2, v2);
        a3 = f32x2_add(a3, v3);
    }
    for (; j < end; j++) {
        int s0 = g_sorted[j];
        u64 v0 = *(const u64*)(g_zy + (size_t)s0 * 128 + 64 + 2 * lane);
        a0 = f32x2_add(a0, v0);
    }
    a0 = f32x2_add(a0, a1);
    a2 = f32x2_add(a2, a3);
    a0 = f32x2_add(a0, a2);

    float sx, sy;
    f32x2_unpack(a0, sx, sy);

    int deg = end - beg;
    float inv = 1.0f / (float)(deg > 0 ? deg : 1);

    float2 z = *(const float2*)(g_zy + (size_t)warp * 128 + 2 * lane);
    float2 o;
    o.x = fmaxf(z.x + sx * inv, 0.f);
    o.y = fmaxf(z.y + sy * inv, 0.f);
    *(float2*)(out + (size_t)warp * 64 + 2 * lane) = o;
}

// ---------------- launch ----------------
// Fork-join: GEMM runs on a second stream concurrently with the CSR build;
// both join before k_aggregate. Same GPU work on every call (streams/events
// are created once; no work is ever skipped or cached).
extern "C" void kernel_launch(void* const* d_in, const int* in_sizes, int n_in,
                              void* d_out, int out_size) {
    const float* x  = (const float*)d_in[0];
    const float* Ws = (const float*)d_in[1];
    const float* Wn = (const float*)d_in[2];
    const float* b  = (const float*)d_in[3];
    const int*   src = (const int*)d_in[4];
    const int*   dst = (const int*)d_in[5];

    int n_src   = in_sizes[0] / FEAT;
    int n_edges = in_sizes[4];
    int num_dst = out_size / FEAT;
    float* out  = (float*)d_out;

    static cudaStream_t s_gemm = nullptr;
    static cudaEvent_t  ev_fork = nullptr;
    static cudaEvent_t  ev_join = nullptr;
    if (s_gemm == nullptr) {
        cudaStreamCreateWithFlags(&s_gemm, cudaStreamNonBlocking);
        cudaEventCreateWithFlags(&ev_fork, cudaEventDisableTiming);
        cudaEventCreateWithFlags(&ev_join, cudaEventDisableTiming);
    }

    int tb = 256;
    int gb_nodes = (num_dst + tb - 1) / tb;
    int gb_edges = (n_edges + tb - 1) / tb;
    int nb_scan  = (num_dst + SCAN_BLK - 1) / SCAN_BLK;

    // fork: GEMM branch on s_gemm
    cudaEventRecord(ev_fork, 0);
    cudaStreamWaitEvent(s_gemm, ev_fork, 0);
    int gemm_blocks = (n_src + 63) / 64;
    k_gemm_zy<<<gemm_blocks, 256, 0, s_gemm>>>(x, Ws, Wn, b, n_src);
    cudaEventRecord(ev_join, s_gemm);

    // CSR build branch on the main (capture) stream
    k_zero_deg<<<gb_nodes, tb>>>(num_dst);
    k_hist<<<gb_edges, tb>>>(dst, n_edges);
    k_scan1<<<nb_scan, SCAN_BLK>>>(num_dst);
    k_scan2<<<1, 128>>>(nb_scan);
    k_scan3<<<gb_nodes, tb>>>(num_dst, n_edges);
    k_scatter<<<gb_edges, tb>>>(src, dst, n_edges);

    // join: aggregate needs both CSR and zy
    cudaStreamWaitEvent(0, ev_join, 0);
    int agg_blocks = (num_dst * 32 + tb - 1) / tb;
    k_aggregate<<<agg_blocks, tb>>>(out, num_dst);
}

// round 5
// speedup vs baseline: 1.5972x; 1.0259x over previous
#include <cuda_runtime.h>
#include <cstdint>

typedef unsigned long long u64;
typedef unsigned int u32;

// ---------------- problem-size constants ----------------
#define MAX_NODES 100000
#define MAX_EDGES 1000000
#define FEAT      64
#define SCAN_BLK  1024
#define MAX_SCAN_BLOCKS ((MAX_NODES + SCAN_BLK - 1) / SCAN_BLK)   // 98

// ---------------- device scratch ----------------
// deg + lookback status share one region so a single memset clears both.
struct ZeroRegion {
    int deg[MAX_NODES];
    u32 status[MAX_SCAN_BLOCKS];    // [31:30]=flag (0 inv,1 agg,2 prefix), [29:0]=value
};
__device__ ZeroRegion g_zz;
__device__ int   g_off[MAX_NODES + 1];
__device__ int   g_cur[MAX_NODES];
__device__ int   g_sorted[MAX_EDGES];
// zy[row][0..63]  = x @ W_self + b   (z, used at dst)
// zy[row][64..127]= x @ W_neigh      (y, gathered via src)
__device__ float g_zy[(size_t)MAX_NODES * 128];

#define FLAG_AGG    (1u << 30)
#define FLAG_PREFIX (2u << 30)
#define VAL_MASK    0x3FFFFFFFu

// ---------------- packed f32x2 helpers (Blackwell FFMA2) ----------------
__device__ __forceinline__ u64 f32x2_dup(float a) {
    u64 r;
    asm("mov.b64 %0, {%1, %1};" : "=l"(r) : "f"(a));
    return r;
}
__device__ __forceinline__ u64 f32x2_fma(u64 a, u64 b, u64 c) {
    u64 d;
    asm("fma.rn.f32x2 %0, %1, %2, %3;" : "=l"(d) : "l"(a), "l"(b), "l"(c));
    return d;
}
__device__ __forceinline__ u64 f32x2_add(u64 a, u64 b) {
    u64 d;
    asm("add.rn.f32x2 %0, %1, %2;" : "=l"(d) : "l"(a), "l"(b));
    return d;
}
__device__ __forceinline__ void f32x2_unpack(u64 v, float& lo, float& hi) {
    asm("mov.b64 {%0, %1}, %2;" : "=f"(lo), "=f"(hi) : "l"(v));
}

// ---------------- 1) degree histogram (4 edges / thread) ----------------
__global__ void k_hist(const int* __restrict__ dst, int n_edges) {
    int q = blockIdx.x * blockDim.x + threadIdx.x;      // quad index
    int e = q * 4;
    if (e + 3 < n_edges) {
        int4 d = *(const int4*)(dst + e);
        atomicAdd(&g_zz.deg[d.x], 1);
        atomicAdd(&g_zz.deg[d.y], 1);
        atomicAdd(&g_zz.deg[d.z], 1);
        atomicAdd(&g_zz.deg[d.w], 1);
    } else {
        for (; e < n_edges; e++) atomicAdd(&g_zz.deg[dst[e]], 1);
    }
}

// ---------------- 2) single-kernel scan (decoupled lookback) ----------------
// grid = MAX_SCAN_BLOCKS (<=148 SMs, all tiles resident -> no deadlock).
// Produces g_off (exclusive prefix), g_cur (=g_off), g_off[n]=n_edges.
__global__ __launch_bounds__(SCAN_BLK) void k_scan(int n, int n_edges) {
    __shared__ int ws[32];
    __shared__ int sPrefix;

    int tile = blockIdx.x;
    int i    = tile * SCAN_BLK + threadIdx.x;
    int lane = threadIdx.x & 31;
    int wid  = threadIdx.x >> 5;

    int v    = (i < n) ? g_zz.deg[i] : 0;
    int orig = v;
    #pragma unroll
    for (int o = 1; o < 32; o <<= 1) {
        int t = __shfl_up_sync(0xffffffffu, v, o);
        if (lane >= o) v += t;
    }
    if (lane == 31) ws[wid] = v;
    __syncthreads();
    if (wid == 0) {
        int w = ws[lane];
        #pragma unroll
        for (int o = 1; o < 32; o <<= 1) {
            int t = __shfl_up_sync(0xffffffffu, w, o);
            if (lane >= o) w += t;
        }
        ws[lane] = w;
    }
    __syncthreads();
    int base  = wid ? ws[wid - 1] : 0;
    int total = ws[31];

    // warp 0: publish + lookback (unsigned flags — bit31 is data, not sign)
    if (wid == 0) {
        if (tile == 0) {
            if (lane == 0) {
                atomicExch(&g_zz.status[0], FLAG_PREFIX | (u32)total);
                sPrefix = 0;
            }
        } else {
            if (lane == 0)
                atomicExch(&g_zz.status[tile], FLAG_AGG | (u32)total);

            int prefix = 0;
            int base_t = tile - 1;
            while (base_t >= 0) {
                int t = base_t - lane;
                u32 s = 0;
                if (t >= 0) {
                    do { s = *(volatile u32*)&g_zz.status[t]; } while ((s >> 30) == 0u);
                }
                unsigned pm = __ballot_sync(0xffffffffu, t >= 0 && ((s >> 30) == 2u));
                int val = (int)(s & VAL_MASK);
                if (pm) {
                    int firstP  = __ffs(pm) - 1;   // nearest predecessor with prefix
                    int contrib = (lane <= firstP) ? val : 0;
                    #pragma unroll
                    for (int o = 16; o; o >>= 1)
                        contrib += __shfl_xor_sync(0xffffffffu, contrib, o);
                    prefix += contrib;
                    break;
                } else {
                    int contrib = (t >= 0) ? val : 0;
                    #pragma unroll
                    for (int o = 16; o; o >>= 1)
                        contrib += __shfl_xor_sync(0xffffffffu, contrib, o);
                    prefix += contrib;
                    base_t -= 32;
                }
            }
            if (lane == 0) {
                atomicExch(&g_zz.status[tile], FLAG_PREFIX | (u32)(prefix + total));
                sPrefix = prefix;
            }
        }
    }
    __syncthreads();

    if (i < n) {
        int o = sPrefix + base + v - orig;
        g_off[i] = o;
        g_cur[i] = o;
    }
    if (tile == gridDim.x - 1 && threadIdx.x == 0) g_off[n] = n_edges;
}

// ---------------- 3) counting-sort scatter (4 edges / thread) ----------------
__global__ void k_scatter(const int* __restrict__ src, const int* __restrict__ dst,
                          int n_edges) {
    int q = blockIdx.x * blockDim.x + threadIdx.x;
    int e = q * 4;
    if (e + 3 < n_edges) {
        int4 d = *(const int4*)(dst + e);
        int4 s = *(const int4*)(src + e);
        g_sorted[atomicAdd(&g_cur[d.x], 1)] = s.x;
        g_sorted[atomicAdd(&g_cur[d.y], 1)] = s.y;
        g_sorted[atomicAdd(&g_cur[d.z], 1)] = s.z;
        g_sorted[atomicAdd(&g_cur[d.w], 1)] = s.w;
    } else {
        for (; e < n_edges; e++)
            g_sorted[atomicAdd(&g_cur[dst[e]], 1)] = src[e];
    }
}

// ---------------- 4) zy = [ x@W_self + b | x@W_neigh ], FFMA2 tile ----------------
#define XT_PITCH 66
__global__ __launch_bounds__(256) void k_gemm_zy(
    const float* __restrict__ x,
    const float* __restrict__ Ws,
    const float* __restrict__ Wn,
    const float* __restrict__ b,
    int n)
{
    __shared__ float sXT[64][XT_PITCH];   // transposed: sXT[k][row]
    __shared__ float sW[64][128];
    __shared__ float sB[64];

    int tid = threadIdx.x;
    int r0  = blockIdx.x * 64;

    for (int i = tid; i < 2048; i += 256) {
        int k  = i >> 5;
        int c4 = i & 31;
        float4 v = (c4 < 16) ? ((const float4*)Ws)[k * 16 + c4]
                             : ((const float4*)Wn)[k * 16 + (c4 - 16)];
        ((float4*)&sW[k][0])[c4] = v;
    }
    if (tid < 64) sB[tid] = b[tid];

    for (int i = tid; i < 1024; i += 256) {
        int r  = i >> 4;
        int c4 = i & 15;
        int gr = r0 + r;
        float4 v = make_float4(0.f, 0.f, 0.f, 0.f);
        if (gr < n) v = ((const float4*)x)[(size_t)gr * 16 + c4];
        int k = c4 * 4;
        sXT[k + 0][r] = v.x;
        sXT[k + 1][r] = v.y;
        sXT[k + 2][r] = v.z;
        sXT[k + 3][r] = v.w;
    }
    __syncthreads();

    int cg = (tid & 31) * 4;      // 4 output columns
    int rg = (tid >> 5) * 8;      // 8 output rows = 4 row-pairs

    u64 acc[4][4];
    #pragma unroll
    for (int t = 0; t < 4; t++)
        #pragma unroll
        for (int c = 0; c < 4; c++) acc[t][c] = 0ull;

    #pragma unroll 4
    for (int k = 0; k < 64; k++) {
        u64 a2[4];
        #pragma unroll
        for (int t = 0; t < 4; t++)
            a2[t] = *(const u64*)&sXT[k][rg + 2 * t];

        float4 wv = *(const float4*)&sW[k][cg];
        u64 w0 = f32x2_dup(wv.x);
        u64 w1 = f32x2_dup(wv.y);
        u64 w2 = f32x2_dup(wv.z);
        u64 w3 = f32x2_dup(wv.w);

        #pragma unroll
        for (int t = 0; t < 4; t++) {
            acc[t][0] = f32x2_fma(a2[t], w0, acc[t][0]);
            acc[t][1] = f32x2_fma(a2[t], w1, acc[t][1]);
            acc[t][2] = f32x2_fma(a2[t], w2, acc[t][2]);
            acc[t][3] = f32x2_fma(a2[t], w3, acc[t][3]);
        }
    }

    float4 bias = make_float4(0.f, 0.f, 0.f, 0.f);
    if (cg < 64) bias = *(const float4*)&sB[cg];

    #pragma unroll
    for (int t = 0; t < 4; t++) {
        float lo[4], hi[4];
        #pragma unroll
        for (int c = 0; c < 4; c++) f32x2_unpack(acc[t][c], lo[c], hi[c]);
        int gr0 = r0 + rg + 2 * t;
        if (gr0 < n) {
            float4 o0 = make_float4(lo[0] + bias.x, lo[1] + bias.y,
                                    lo[2] + bias.z, lo[3] + bias.w);
            *(float4*)&g_zy[(size_t)gr0 * 128 + cg] = o0;
        }
        if (gr0 + 1 < n) {
            float4 o1 = make_float4(hi[0] + bias.x, hi[1] + bias.y,
                                    hi[2] + bias.z, hi[3] + bias.w);
            *(float4*)&g_zy[(size_t)(gr0 + 1) * 128 + cg] = o1;
        }
    }
}

// ---------------- 5) per-dst aggregation + epilogue ----------------
__global__ __launch_bounds__(256) void k_aggregate(float* __restrict__ out, int num_dst) {
    int warp = (blockIdx.x * blockDim.x + threadIdx.x) >> 5;
    int lane = threadIdx.x & 31;
    if (warp >= num_dst) return;

    int beg = g_off[warp];
    int end = g_off[warp + 1];

    u64 a0 = 0ull, a1 = 0ull, a2 = 0ull, a3 = 0ull;
    int j = beg;
    for (; j + 3 < end; j += 4) {
        int s0 = g_sorted[j];
        int s1 = g_sorted[j + 1];
        int s2 = g_sorted[j + 2];
        int s3 = g_sorted[j + 3];
        u64 v0 = *(const u64*)(g_zy + (size_t)s0 * 128 + 64 + 2 * lane);
        u64 v1 = *(const u64*)(g_zy + (size_t)s1 * 128 + 64 + 2 * lane);
        u64 v2 = *(const u64*)(g_zy + (size_t)s2 * 128 + 64 + 2 * lane);
        u64 v3 = *(const u64*)(g_zy + (size_t)s3 * 128 + 64 + 2 * lane);
        a0 = f32x2_add(a0, v0);
        a1 = f32x2_add(a1, v1);
        a2 = f32x2_add(a2, v2);
        a3 = f32x2_add(a3, v3);
    }
    for (; j < end; j++) {
        int s0 = g_sorted[j];
        u64 v0 = *(const u64*)(g_zy + (size_t)s0 * 128 + 64 + 2 * lane);
        a0 = f32x2_add(a0, v0);
    }
    a0 = f32x2_add(a0, a1);
    a2 = f32x2_add(a2, a3);
    a0 = f32x2_add(a0, a2);

    float sx, sy;
    f32x2_unpack(a0, sx, sy);

    int deg = end - beg;
    float inv = 1.0f / (float)(deg > 0 ? deg : 1);

    float2 z = *(const float2*)(g_zy + (size_t)warp * 128 + 2 * lane);
    float2 o;
    o.x = fmaxf(z.x + sx * inv, 0.f);
    o.y = fmaxf(z.y + sy * inv, 0.f);
    *(float2*)(out + (size_t)warp * 64 + 2 * lane) = o;
}

// ---------------- launch ----------------
extern "C" void kernel_launch(void* const* d_in, const int* in_sizes, int n_in,
                              void* d_out, int out_size) {
    const float* x  = (const float*)d_in[0];
    const float* Ws = (const float*)d_in[1];
    const float* Wn = (const float*)d_in[2];
    const float* b  = (const float*)d_in[3];
    const int*   src = (const int*)d_in[4];
    const int*   dst = (const int*)d_in[5];

    int n_src   = in_sizes[0] / FEAT;
    int n_edges = in_sizes[4];
    int num_dst = out_size / FEAT;
    float* out  = (float*)d_out;

    static cudaStream_t s_gemm  = nullptr;
    static cudaEvent_t  ev_fork = nullptr;
    static cudaEvent_t  ev_join = nullptr;
    static void*        p_zz    = nullptr;
    if (s_gemm == nullptr) {
        cudaStreamCreateWithFlags(&s_gemm, cudaStreamNonBlocking);
        cudaEventCreateWithFlags(&ev_fork, cudaEventDisableTiming);
        cudaEventCreateWithFlags(&ev_join, cudaEventDisableTiming);
        cudaGetSymbolAddress(&p_zz, g_zz);
    }

    // fork: GEMM on side stream
    cudaEventRecord(ev_fork, 0);
    cudaStreamWaitEvent(s_gemm, ev_fork, 0);
    int gemm_blocks = (n_src + 63) / 64;
    k_gemm_zy<<<gemm_blocks, 256, 0, s_gemm>>>(x, Ws, Wn, b, n_src);
    cudaEventRecord(ev_join, s_gemm);

    // CSR build chain (short): memset -> hist -> scan -> scatter
    cudaMemsetAsync(p_zz, 0, sizeof(ZeroRegion), 0);

    int tb = 256;
    int quads    = (n_edges + 3) / 4;
    int gb_quads = (quads + tb - 1) / tb;
    int nb_scan  = (num_dst + SCAN_BLK - 1) / SCAN_BLK;

    k_hist<<<gb_quads, tb>>>(dst, n_edges);
    k_scan<<<nb_scan, SCAN_BLK>>>(num_dst, n_edges);
    k_scatter<<<gb_quads, tb>>>(src, dst, n_edges);

    // join: aggregate needs both CSR and zy
    cudaStreamWaitEvent(0, ev_join, 0);
    int agg_blocks = (num_dst * 32 + tb - 1) / tb;
    k_aggregate<<<agg_blocks, tb>>>(out, num_dst);
}